// round 9
// baseline (speedup 1.0000x reference)
#include <cuda_runtime.h>
#include <cuda_bf16.h>
#include <cstdint>

#define B_ 256
#define A_ 100
#define NB_ 10
#define BOND_ 110
#define AF_ 82
#define BF_ 6
#define H_ 300
#define MROWS (B_*A_)       // 25600
#define BROWS (B_*BOND_)    // 28160
#define KP 320              // padded K for H (10 chunks of 32)
#define KPAF 96             // padded K for AF (3 chunks)

typedef __nv_bfloat16 bf16;

// ---------------- scratch (device globals; zero-initialized at load) --------
__device__ __align__(256) bf16  g_h_hi [MROWS*KP];
__device__ __align__(256) bf16  g_h_lo [MROWS*KP];
__device__ __align__(256) bf16  g_n_hi [MROWS*KP];
__device__ __align__(256) bf16  g_n_lo [MROWS*KP];
__device__ __align__(256) bf16  g_af_hi[MROWS*KPAF];
__device__ __align__(256) bf16  g_af_lo[MROWS*KPAF];
__device__ __align__(256) float g_hW   [MROWS*KP];   // compact dense, stride 320
__device__ __align__(256) float g_hAcc [MROWS*KP];   // compact dense, stride 320
__device__ __align__(256) float g_bW   [BROWS*H_];
__device__ __align__(256) float g_bW2  [BROWS*H_];
// transposed+split weights [640][KPx]; pad regions stay zero (never written)
__device__ __align__(256) bf16  g_wfc1_hi[640*KPAF];
__device__ __align__(256) bf16  g_wfc1_lo[640*KPAF];
__device__ __align__(256) bf16  g_wG1_hi[640*KP];
__device__ __align__(256) bf16  g_wG1_lo[640*KP];
__device__ __align__(256) bf16  g_wG2_hi[640*KP];
__device__ __align__(256) bf16  g_wG2_lo[640*KP];
__device__ __align__(256) bf16  g_wF_hi [640*KP];
__device__ __align__(256) bf16  g_wF_lo [640*KP];

// ---------------- helpers ----------------------------------------------------
__device__ __forceinline__ uint32_t smem_u32(const void* p) {
    uint32_t a;
    asm("{ .reg .u64 t; cvta.to.shared.u64 t, %1; cvt.u32.u64 %0, t; }"
        : "=r"(a) : "l"(p));
    return a;
}
// SW128 layout for a [rows][32 bf16] tile: 2 logical rows per 128B phys row
__device__ __forceinline__ uint32_t swz_off(int r, int c16) {
    uint32_t phys = ((uint32_t)(r >> 1) << 7) | ((uint32_t)(r & 1) << 6) | ((uint32_t)c16 << 4);
    return phys ^ ((phys >> 3) & 0x70);
}
__device__ __forceinline__ void cpasync16(uint32_t dst, const void* src) {
    asm volatile("cp.async.cg.shared.global [%0], [%1], 16;" :: "r"(dst), "l"(src));
}
#define CP_COMMIT() asm volatile("cp.async.commit_group;" ::: "memory")
#define CP_WAIT(n)  asm volatile("cp.async.wait_group %0;" :: "n"(n) : "memory")

__device__ __forceinline__ void ldsm_x4(uint32_t* r, uint32_t addr) {
    asm volatile("ldmatrix.sync.aligned.m8n8.x4.shared.b16 {%0,%1,%2,%3}, [%4];"
        : "=r"(r[0]), "=r"(r[1]), "=r"(r[2]), "=r"(r[3]) : "r"(addr));
}
__device__ __forceinline__ void mma_bf16(float* d, const uint32_t* a,
                                         uint32_t b0, uint32_t b1) {
    asm volatile(
        "mma.sync.aligned.m16n8k16.row.col.f32.bf16.bf16.f32 "
        "{%0,%1,%2,%3}, {%4,%5,%6,%7}, {%8,%9}, {%0,%1,%2,%3};"
        : "+f"(d[0]), "+f"(d[1]), "+f"(d[2]), "+f"(d[3])
        : "r"(a[0]), "r"(a[1]), "r"(a[2]), "r"(a[3]), "r"(b0), "r"(b1));
}
__device__ __forceinline__ void bsplit(float v, uint16_t& h, uint16_t& l) {
    __nv_bfloat16 bh = __float2bfloat16(v);
    float r = v - __bfloat162float(bh);
    __nv_bfloat16 bl = __float2bfloat16(r);
    h = __bfloat16_as_ushort(bh);
    l = __bfloat16_as_ushort(bl);
}

// ============================================================================
// bf16-split tensor-core GEMM, CTA tile 128x128, BK=32, 512 thr (16 warps).
// Warps: 8(m) x 2(n); warp tile 16x64 -> 32 accum regs/thread, ~80 regs total,
// 2 CTAs/SM = 32 warps/SM for latency hiding.
// 3 products: AhBh + AlBh + AhBl. Single-barrier 3-stage cp.async pipeline.
// ks_last=1 skips the all-zero final 16-wide k-step of K=300-in-320 operands.
// smem/stage: Ah 8K | Al 8K | Bh 8K | Bl 8K = 32KB. 3 stages = 96KB.
// ============================================================================
#define STAGE_BYTES 32768
#define NSTAGE 3

__global__ __launch_bounds__(512, 2)
void gemm_mma(const bf16* __restrict__ Ah, const bf16* __restrict__ Al,
              int KPa, int nch, int ks_last,
              const bf16* __restrict__ Bh, const bf16* __restrict__ Bl,
              int Nvalid,
              float* __restrict__ W1out, float* __restrict__ W2out,
              bf16* __restrict__ out_hi, bf16* __restrict__ out_lo,
              const float* __restrict__ bias,
              const float* __restrict__ accp,
              int relu_flag, int mode)
{
    extern __shared__ char sm[];
    const uint32_t sb = smem_u32(sm);
    const int tid = threadIdx.x;
    const int lane = tid & 31;
    const int wid = tid >> 5;          // 0..15
    const int widm = wid & 7;          // 0..7 -> m base widm*16
    const int widn = wid >> 3;         // 0..1 -> n base widn*64
    const int rowBase = blockIdx.y * 128;
    const int colBase = blockIdx.x * 128;

    auto issue = [&](int c, int s) {
        const uint32_t base = sb + s * STAGE_BYTES;
        #pragma unroll
        for (int t = 0; t < 2; t++) {                 // A: 1024 x 16B
            int i = tid + (t << 9);
            int which = i >> 9;
            int rem = i & 511;
            int r = rem >> 2, c16 = rem & 3;
            const bf16* srcb = which ? Al : Ah;
            uint32_t dst = base + which * 8192 + swz_off(r, c16);
            cpasync16(dst, srcb + (size_t)(rowBase + r) * KPa + c * 32 + c16 * 8);
        }
        #pragma unroll
        for (int t = 0; t < 2; t++) {                 // B: 1024 x 16B
            int i = tid + (t << 9);
            int which = i >> 9;
            int rem = i & 511;
            int r = rem >> 2, c16 = rem & 3;
            const bf16* srcb = which ? Bl : Bh;
            uint32_t dst = base + 16384 + which * 8192 + swz_off(r, c16);
            cpasync16(dst, srcb + (size_t)(colBase + r) * KPa + c * 32 + c16 * 8);
        }
        CP_COMMIT();
    };

    float d[8][4];
    #pragma unroll
    for (int j = 0; j < 8; j++)
        #pragma unroll
        for (int k = 0; k < 4; k++) d[j][k] = 0.f;

    const int lr = lane & 7;
    const int gA_row = ((lane >> 3) & 1) * 8;
    const int gA_c16 = lane >> 4;
    const int gB_row = ((lane >> 4) & 1) * 8;
    const int gB_c16 = (lane >> 3) & 1;

    // one 16-wide k-step of the current chunk
    auto compute_ks = [&](uint32_t base, int ks) {
        uint32_t ah[4], al[4];
        {
            int r = widm * 16 + lr + gA_row;
            int c16 = ks * 2 + gA_c16;
            uint32_t o = swz_off(r, c16);
            ldsm_x4(ah, base + o);
            ldsm_x4(al, base + 8192 + o);
        }
        #pragma unroll
        for (int pr = 0; pr < 4; pr++) {
            int r = widn * 64 + pr * 16 + lr + gB_row;
            int c16 = ks * 2 + gB_c16;
            uint32_t o = swz_off(r, c16);
            {
                uint32_t bh[4];
                ldsm_x4(bh, base + 16384 + o);
                #pragma unroll
                for (int oo = 0; oo < 2; oo++) {
                    mma_bf16(d[pr*2+oo], ah, bh[oo*2], bh[oo*2+1]);
                    mma_bf16(d[pr*2+oo], al, bh[oo*2], bh[oo*2+1]);
                }
            }
            {
                uint32_t bl[4];
                ldsm_x4(bl, base + 24576 + o);
                #pragma unroll
                for (int oo = 0; oo < 2; oo++)
                    mma_bf16(d[pr*2+oo], ah, bl[oo*2], bl[oo*2+1]);
            }
        }
    };

    // prologue: 2 stages in flight
    issue(0, 0);
    if (nch > 1) issue(1, 1);

    for (int c = 0; c < nch; c++) {
        if (c + 1 < nch) CP_WAIT(1); else CP_WAIT(0);  // group c complete
        __syncthreads();               // compute(c-1) done -> slot (c+2)%3 free
        if (c + 2 < nch) issue(c + 2, (c + 2) % NSTAGE);

        const uint32_t base = sb + (c % NSTAGE) * STAGE_BYTES;
        compute_ks(base, 0);
        if (c + 1 < nch || ks_last == 2) compute_ks(base, 1);
    }

    // ---- epilogue ----
    #pragma unroll
    for (int nt = 0; nt < 8; nt++) {
        int col = colBase + widn * 64 + nt * 8 + (lane & 3) * 2;
        if (col >= Nvalid) continue;
        int row0 = rowBase + widm * 16 + (lane >> 2);
        float v[4] = { d[nt][0], d[nt][1], d[nt][2], d[nt][3] };
        if (accp) {
            float2 a0 = *(const float2*)(accp + (size_t)row0 * KP + col);
            float2 a1 = *(const float2*)(accp + (size_t)(row0 + 8) * KP + col);
            v[0] += a0.x; v[1] += a0.y; v[2] += a1.x; v[3] += a1.y;
        }
        if (bias) {
            float2 bb = *(const float2*)(bias + col);
            v[0] += bb.x; v[1] += bb.y; v[2] += bb.x; v[3] += bb.y;
        }
        if (relu_flag) {
            #pragma unroll
            for (int k = 0; k < 4; k++) v[k] = fmaxf(v[k], 0.f);
        }
        if (mode & 1) {
            float* basep = (col < 300) ? (W1out + col) : (W2out + (col - 300));
            *(float2*)(basep + (size_t)row0 * KP) = make_float2(v[0], v[1]);
            *(float2*)(basep + (size_t)(row0 + 8) * KP) = make_float2(v[2], v[3]);
        }
        if (mode & 2) {
            uint16_t h0, l0, h1, l1;
            bsplit(v[0], h0, l0); bsplit(v[1], h1, l1);
            *(uint32_t*)(out_hi + (size_t)row0 * KP + col) = (uint32_t)h0 | ((uint32_t)h1 << 16);
            *(uint32_t*)(out_lo + (size_t)row0 * KP + col) = (uint32_t)l0 | ((uint32_t)l1 << 16);
            bsplit(v[2], h0, l0); bsplit(v[3], h1, l1);
            *(uint32_t*)(out_hi + (size_t)(row0 + 8) * KP + col) = (uint32_t)h0 | ((uint32_t)h1 << 16);
            *(uint32_t*)(out_lo + (size_t)(row0 + 8) * KP + col) = (uint32_t)l0 | ((uint32_t)l1 << 16);
        }
    }
}

// ---------------- merged weight preps ----------------------------------------
__global__ __launch_bounds__(256)
void prep1(const float* __restrict__ w_fc1, const float* __restrict__ w_nei,
           const float* __restrict__ w_atom,
           bf16* __restrict__ fc1h, bf16* __restrict__ fc1l,
           bf16* __restrict__ G1h, bf16* __restrict__ G1l)
{
    int idx = blockIdx.x * blockDim.x + threadIdx.x;
    if (idx < AF_ * 300) {
        int k = idx / 300, n = idx - k * 300;
        uint16_t h, l; bsplit(w_fc1[idx], h, l);
        fc1h[(size_t)n * KPAF + k] = __ushort_as_bfloat16(h);
        fc1l[(size_t)n * KPAF + k] = __ushort_as_bfloat16(l);
        return;
    }
    int j = idx - AF_ * 300;
    if (j >= 300 * 600) return;
    int k = j / 600, n = j - k * 600;
    float v = (n < 300) ? w_nei[k * 300 + n] : w_atom[k * 300 + (n - 300)];
    uint16_t h, l; bsplit(v, h, l);
    G1h[(size_t)n * KP + k] = __ushort_as_bfloat16(h);
    G1l[(size_t)n * KP + k] = __ushort_as_bfloat16(l);
}

__global__ __launch_bounds__(256)
void prep2(const float* __restrict__ w_atom, const float* __restrict__ w2a,
           const float* __restrict__ w_fc2,
           bf16* __restrict__ G2h, bf16* __restrict__ G2l,
           bf16* __restrict__ Fh, bf16* __restrict__ Fl)
{
    int idx = blockIdx.x * blockDim.x + threadIdx.x;
    if (idx < 300 * 300) {
        int k = idx / 300, n = idx - k * 300;
        uint16_t h, l; bsplit(w_atom[90000 + idx], h, l);
        G2h[(size_t)n * KP + k] = __ushort_as_bfloat16(h);
        G2l[(size_t)n * KP + k] = __ushort_as_bfloat16(l);
        return;
    }
    int j = idx - 300 * 300;
    if (j >= 300 * 600) return;
    int k = j / 600, n = j - k * 600;
    float v = (n < 300) ? w2a[k * 300 + n] : w_fc2[k * 300 + (n - 300)];
    uint16_t h, l; bsplit(v, h, l);
    Fh[(size_t)n * KP + k] = __ushort_as_bfloat16(h);
    Fl[(size_t)n * KP + k] = __ushort_as_bfloat16(l);
}

// ---------------- split atom_feats ------------------------------------------
__global__ __launch_bounds__(256)
void split_af(const float* __restrict__ af, bf16* __restrict__ hi, bf16* __restrict__ lo)
{
    int idx = blockIdx.x * blockDim.x + threadIdx.x;
    if (idx >= MROWS * AF_) return;
    int r = idx / AF_;
    int c = idx - r * AF_;
    uint16_t h, l;
    bsplit(af[idx], h, l);
    hi[(size_t)r * KPAF + c] = __ushort_as_bfloat16(h);
    lo[(size_t)r * KPAF + c] = __ushort_as_bfloat16(l);
}

// ---------------- bond precompute (flat float4; weights L1-resident) --------
#define BPQ (BROWS * 75)
__global__ __launch_bounds__(256)
void bond_pre(const float* __restrict__ bond_feats,
              const float* __restrict__ w_neiB,   // [6][300]
              const float* __restrict__ w2b,      // [6][300]
              float* __restrict__ bW, float* __restrict__ bW2)
{
    int idx = blockIdx.x * blockDim.x + threadIdx.x;
    if (idx >= BPQ) return;
    int row = idx / 75;
    int c4 = idx - row * 75;
    const float* f = bond_feats + row * BF_;
    const float4* w1 = (const float4*)w_neiB;
    const float4* w2 = (const float4*)w2b;
    float4 s1 = make_float4(0.f, 0.f, 0.f, 0.f);
    float4 s2 = make_float4(0.f, 0.f, 0.f, 0.f);
    #pragma unroll
    for (int k = 0; k < BF_; k++) {
        float fk = f[k];
        float4 a = w1[k * 75 + c4];
        float4 b = w2[k * 75 + c4];
        s1.x = fmaf(fk, a.x, s1.x); s1.y = fmaf(fk, a.y, s1.y);
        s1.z = fmaf(fk, a.z, s1.z); s1.w = fmaf(fk, a.w, s1.w);
        s2.x = fmaf(fk, b.x, s2.x); s2.y = fmaf(fk, b.y, s2.y);
        s2.z = fmaf(fk, b.z, s2.z); s2.w = fmaf(fk, b.w, s2.w);
    }
    ((float4*)bW)[idx]  = s1;
    ((float4*)bW2)[idx] = s2;
}

// ---------------- gather+relu+sum -> split nei -------------------------------
__global__ __launch_bounds__(96)
void gather_sum(const float* __restrict__ hW,      // compact, stride KP
                const float* __restrict__ bW,
                const float* __restrict__ b_nei,
                const int* __restrict__ atom_graph,
                const int* __restrict__ bond_graph,
                const int* __restrict__ num_nbs,
                bf16* __restrict__ nei_hi, bf16* __restrict__ nei_lo)
{
    int ba = blockIdx.x;
    __shared__ int hidx[NB_], bidx[NB_];
    __shared__ int nn;
    if (threadIdx.x == 0) nn = num_nbs[ba];
    if (threadIdx.x < NB_) {
        int j = threadIdx.x;
        int ab = atom_graph[((size_t)ba * NB_ + j) * 2 + 0];
        int aa = atom_graph[((size_t)ba * NB_ + j) * 2 + 1];
        hidx[j] = (ab * A_ + aa) * (KP / 4);
        int bb = bond_graph[((size_t)ba * NB_ + j) * 2 + 0];
        int be = bond_graph[((size_t)ba * NB_ + j) * 2 + 1];
        bidx[j] = (bb * BOND_ + be) * (H_ / 4);
    }
    __syncthreads();
    int t = threadIdx.x;
    if (t >= H_ / 4) return;
    int n = nn;
    const float4* h4 = (const float4*)hW;
    const float4* b4 = (const float4*)bW;
    float4 bias4 = ((const float4*)b_nei)[t];
    float4 acc = make_float4(0.f, 0.f, 0.f, 0.f);
    #pragma unroll 2
    for (int j = 0; j < n; j++) {
        float4 hv = h4[hidx[j] + t];
        float4 bv = b4[bidx[j] + t];
        acc.x += fmaxf(hv.x + bv.x + bias4.x, 0.f);
        acc.y += fmaxf(hv.y + bv.y + bias4.y, 0.f);
        acc.z += fmaxf(hv.z + bv.z + bias4.z, 0.f);
        acc.w += fmaxf(hv.w + bv.w + bias4.w, 0.f);
    }
    uint16_t h0, l0, h1, l1, h2, l2, h3, l3;
    bsplit(acc.x, h0, l0); bsplit(acc.y, h1, l1);
    bsplit(acc.z, h2, l2); bsplit(acc.w, h3, l3);
    uint2 ph = make_uint2((uint32_t)h0 | ((uint32_t)h1 << 16), (uint32_t)h2 | ((uint32_t)h3 << 16));
    uint2 pl = make_uint2((uint32_t)l0 | ((uint32_t)l1 << 16), (uint32_t)l2 | ((uint32_t)l3 << 16));
    *(uint2*)(nei_hi + (size_t)ba * KP + t * 4) = ph;
    *(uint2*)(nei_lo + (size_t)ba * KP + t * 4) = pl;
}

// ---------------- final elementwise ------------------------------------------
__global__ __launch_bounds__(96)
void final_k(const float* __restrict__ hw2a,   // compact, stride KP
             const float* __restrict__ hfc2,   // compact, stride KP
             const float* __restrict__ bW2,
             const int* __restrict__ atom_graph,
             const int* __restrict__ bond_graph,
             const int* __restrict__ num_nbs,
             const int* __restrict__ n_atoms,
             float* __restrict__ out)
{
    int ba = blockIdx.x;
    int b = ba / A_;
    int a = ba - b * A_;
    __shared__ int hidx[NB_], bidx[NB_];
    __shared__ int nn, nat;
    if (threadIdx.x == 0) { nn = num_nbs[ba]; nat = n_atoms[b]; }
    if (threadIdx.x < NB_) {
        int j = threadIdx.x;
        int ab = atom_graph[((size_t)ba * NB_ + j) * 2 + 0];
        int aa = atom_graph[((size_t)ba * NB_ + j) * 2 + 1];
        hidx[j] = (ab * A_ + aa) * (KP / 4);
        int bb = bond_graph[((size_t)ba * NB_ + j) * 2 + 0];
        int be = bond_graph[((size_t)ba * NB_ + j) * 2 + 1];
        bidx[j] = (bb * BOND_ + be) * (H_ / 4);
    }
    __syncthreads();
    int t = threadIdx.x;
    if (t >= H_ / 4) return;
    int n = nn;
    bool active = a < nat;
    const float4* A4 = (const float4*)hw2a;
    const float4* B4 = (const float4*)bW2;
    float4 acc = make_float4(0.f, 0.f, 0.f, 0.f);
    #pragma unroll 2
    for (int j = 0; j < n; j++) {
        float4 av = A4[hidx[j] + t];
        float4 bv = B4[bidx[j] + t];
        acc.x = fmaf(av.x, bv.x, acc.x);
        acc.y = fmaf(av.y, bv.y, acc.y);
        acc.z = fmaf(av.z, bv.z, acc.z);
        acc.w = fmaf(av.w, bv.w, acc.w);
    }
    float4 res = make_float4(0.f, 0.f, 0.f, 0.f);
    if (active) {
        float4 fv = ((const float4*)hfc2)[(size_t)ba * (KP / 4) + t];
        res.x = fv.x * acc.x; res.y = fv.y * acc.y;
        res.z = fv.z * acc.z; res.w = fv.w * acc.w;
    }
    ((float4*)out)[(size_t)ba * (H_ / 4) + t] = res;
}

// ---------------- launch ------------------------------------------------------
extern "C" void kernel_launch(void* const* d_in, const int* in_sizes, int n_in,
                              void* d_out, int out_size)
{
    const float* atom_feats = (const float*)d_in[0];
    const float* bond_feats = (const float*)d_in[1];
    const float* w_fc1      = (const float*)d_in[2];
    const float* w_nei      = (const float*)d_in[3];
    const float* b_nei      = (const float*)d_in[4];
    const float* w_atom     = (const float*)d_in[5];
    const float* b_atom     = (const float*)d_in[6];
    const float* w2a        = (const float*)d_in[7];
    const float* w2b        = (const float*)d_in[8];
    const float* w_fc2      = (const float*)d_in[9];
    const int*   atom_graph = (const int*)d_in[10];
    const int*   bond_graph = (const int*)d_in[11];
    const int*   num_nbs    = (const int*)d_in[12];
    const int*   n_atoms    = (const int*)d_in[13];
    float* out = (float*)d_out;

    bf16 *h_hi, *h_lo, *n_hi, *n_lo, *af_hi, *af_lo;
    bf16 *wfc1_hi, *wfc1_lo, *wG1_hi, *wG1_lo, *wG2_hi, *wG2_lo, *wF_hi, *wF_lo;
    float *hW, *hAcc, *bW, *bW2;
    cudaGetSymbolAddress((void**)&h_hi, g_h_hi);
    cudaGetSymbolAddress((void**)&h_lo, g_h_lo);
    cudaGetSymbolAddress((void**)&n_hi, g_n_hi);
    cudaGetSymbolAddress((void**)&n_lo, g_n_lo);
    cudaGetSymbolAddress((void**)&af_hi, g_af_hi);
    cudaGetSymbolAddress((void**)&af_lo, g_af_lo);
    cudaGetSymbolAddress((void**)&hW, g_hW);
    cudaGetSymbolAddress((void**)&hAcc, g_hAcc);
    cudaGetSymbolAddress((void**)&bW, g_bW);
    cudaGetSymbolAddress((void**)&bW2, g_bW2);
    cudaGetSymbolAddress((void**)&wfc1_hi, g_wfc1_hi);
    cudaGetSymbolAddress((void**)&wfc1_lo, g_wfc1_lo);
    cudaGetSymbolAddress((void**)&wG1_hi, g_wG1_hi);
    cudaGetSymbolAddress((void**)&wG1_lo, g_wG1_lo);
    cudaGetSymbolAddress((void**)&wG2_hi, g_wG2_hi);
    cudaGetSymbolAddress((void**)&wG2_lo, g_wG2_lo);
    cudaGetSymbolAddress((void**)&wF_hi, g_wF_hi);
    cudaGetSymbolAddress((void**)&wF_lo, g_wF_lo);

    cudaFuncSetAttribute(gemm_mma, cudaFuncAttributeMaxDynamicSharedMemorySize,
                         NSTAGE * STAGE_BYTES);
    const int SMB = NSTAGE * STAGE_BYTES;
    dim3 gN600(5, MROWS / 128);   // cols 0..639, Nvalid=600
    dim3 gN300(3, MROWS / 128);   // cols 0..383, Nvalid=300

    // Order: launch #4 (captured by ncu) = big N600 GEMM.
    prep1<<<(AF_ * 300 + 300 * 600 + 255) / 256, 256>>>(
        w_fc1, w_nei, w_atom, wfc1_hi, wfc1_lo, wG1_hi, wG1_lo);
    split_af<<<(MROWS * AF_ + 255) / 256, 256>>>(atom_feats, af_hi, af_lo);
    // h = relu(af @ w_fc1) -> split   (K=82 real; both ks of last chunk needed)
    gemm_mma<<<gN300, 512, SMB>>>(af_hi, af_lo, KPAF, KPAF / 32, 2, wfc1_hi, wfc1_lo,
                                  300, nullptr, nullptr, h_hi, h_lo,
                                  nullptr, nullptr, 1, 2);
    // (PROFILED) hW = h@w_neiA ; hAcc = h@w_atom_top   (K=300 -> skip zero ks)
    gemm_mma<<<gN600, 512, SMB>>>(h_hi, h_lo, KP, KP / 32, 1, wG1_hi, wG1_lo,
                                  600, hW, hAcc, nullptr, nullptr,
                                  nullptr, nullptr, 0, 1);
    prep2<<<(300 * 300 + 300 * 600 + 255) / 256, 256>>>(
        w_atom, w2a, w_fc2, wG2_hi, wG2_lo, wF_hi, wF_lo);
    bond_pre<<<(BPQ + 255) / 256, 256>>>(bond_feats, w_nei + (size_t)H_ * H_, w2b, bW, bW2);

    // iteration 0 remainder
    gather_sum<<<MROWS, 96>>>(hW, bW, b_nei, atom_graph, bond_graph,
                              num_nbs, n_hi, n_lo);
    gemm_mma<<<gN300, 512, SMB>>>(n_hi, n_lo, KP, KP / 32, 1, wG2_hi, wG2_lo,
                                  300, nullptr, nullptr, h_hi, h_lo,
                                  b_atom, hAcc, 1, 2);
    // iteration 1
    gemm_mma<<<gN600, 512, SMB>>>(h_hi, h_lo, KP, KP / 32, 1, wG1_hi, wG1_lo,
                                  600, hW, hAcc, nullptr, nullptr,
                                  nullptr, nullptr, 0, 1);
    gather_sum<<<MROWS, 96>>>(hW, bW, b_nei, atom_graph, bond_graph,
                              num_nbs, n_hi, n_lo);
    gemm_mma<<<gN300, 512, SMB>>>(n_hi, n_lo, KP, KP / 32, 1, wG2_hi, wG2_lo,
                                  300, nullptr, nullptr, h_hi, h_lo,
                                  b_atom, hAcc, 1, 2);
    // final: hW = h@w2a ; hAcc = h@w_fc2
    gemm_mma<<<gN600, 512, SMB>>>(h_hi, h_lo, KP, KP / 32, 1, wF_hi, wF_lo,
                                  600, hW, hAcc, nullptr, nullptr,
                                  nullptr, nullptr, 0, 1);
    final_k<<<MROWS, 96>>>(hW, hAcc, bW2, atom_graph, bond_graph,
                           num_nbs, n_atoms, out);
}

// round 10
// speedup vs baseline: 1.0394x; 1.0394x over previous
#include <cuda_runtime.h>
#include <cuda_bf16.h>
#include <cstdint>

#define B_ 256
#define A_ 100
#define NB_ 10
#define BOND_ 110
#define AF_ 82
#define BF_ 6
#define H_ 300
#define MROWS (B_*A_)       // 25600
#define BROWS (B_*BOND_)    // 28160
#define KP 320              // padded K stride for H buffers
#define KPAF 96             // padded K stride for atom-feature buffers

typedef __nv_bfloat16 bf16;

// ---------------- scratch (device globals; zero-initialized at load) --------
__device__ __align__(256) bf16  g_h_hi [MROWS*KP];
__device__ __align__(256) bf16  g_h_lo [MROWS*KP];
__device__ __align__(256) bf16  g_n_hi [MROWS*KP];
__device__ __align__(256) bf16  g_n_lo [MROWS*KP];
__device__ __align__(256) bf16  g_af_hi[MROWS*KPAF];
__device__ __align__(256) bf16  g_af_lo[MROWS*KPAF];
__device__ __align__(256) float g_hW   [MROWS*KP];   // compact dense, stride 320
__device__ __align__(256) float g_hF2  [MROWS*KP];   // final hfc2, stride 320
__device__ __align__(256) float g_bW   [BROWS*H_];
__device__ __align__(256) float g_bW2  [BROWS*H_];
// transposed+split weights; 640 rows so any colBase+128 read stays in bounds.
__device__ __align__(256) bf16  g_wfc1_hi[640*KPAF];
__device__ __align__(256) bf16  g_wfc1_lo[640*KPAF];
__device__ __align__(256) bf16  g_wG1_hi[640*KP];    // w_neiA^T  [n][k]
__device__ __align__(256) bf16  g_wG1_lo[640*KP];
__device__ __align__(256) bf16  g_wAt_hi[640*640];   // w_atom^T  [n][k<300 -> k ; k>=300 -> 320+k-300]
__device__ __align__(256) bf16  g_wAt_lo[640*640];
__device__ __align__(256) bf16  g_wF_hi [640*KP];    // rows 0-299 w2a^T, 300-599 w_fc2^T
__device__ __align__(256) bf16  g_wF_lo [640*KP];

// ---------------- helpers ----------------------------------------------------
__device__ __forceinline__ uint32_t smem_u32(const void* p) {
    uint32_t a;
    asm("{ .reg .u64 t; cvta.to.shared.u64 t, %1; cvt.u32.u64 %0, t; }"
        : "=r"(a) : "l"(p));
    return a;
}
// SW128 layout for a [rows][32 bf16] tile: 2 logical rows per 128B phys row
__device__ __forceinline__ uint32_t swz_off(int r, int c16) {
    uint32_t phys = ((uint32_t)(r >> 1) << 7) | ((uint32_t)(r & 1) << 6) | ((uint32_t)c16 << 4);
    return phys ^ ((phys >> 3) & 0x70);
}
__device__ __forceinline__ void cpasync16(uint32_t dst, const void* src) {
    asm volatile("cp.async.cg.shared.global [%0], [%1], 16;" :: "r"(dst), "l"(src));
}
#define CP_COMMIT() asm volatile("cp.async.commit_group;" ::: "memory")
#define CP_WAIT(n)  asm volatile("cp.async.wait_group %0;" :: "n"(n) : "memory")

__device__ __forceinline__ void ldsm_x4(uint32_t* r, uint32_t addr) {
    asm volatile("ldmatrix.sync.aligned.m8n8.x4.shared.b16 {%0,%1,%2,%3}, [%4];"
        : "=r"(r[0]), "=r"(r[1]), "=r"(r[2]), "=r"(r[3]) : "r"(addr));
}
__device__ __forceinline__ void mma_bf16(float* d, const uint32_t* a,
                                         uint32_t b0, uint32_t b1) {
    asm volatile(
        "mma.sync.aligned.m16n8k16.row.col.f32.bf16.bf16.f32 "
        "{%0,%1,%2,%3}, {%4,%5,%6,%7}, {%8,%9}, {%0,%1,%2,%3};"
        : "+f"(d[0]), "+f"(d[1]), "+f"(d[2]), "+f"(d[3])
        : "r"(a[0]), "r"(a[1]), "r"(a[2]), "r"(a[3]), "r"(b0), "r"(b1));
}
__device__ __forceinline__ void bsplit(float v, uint16_t& h, uint16_t& l) {
    __nv_bfloat16 bh = __float2bfloat16(v);
    float r = v - __bfloat162float(bh);
    __nv_bfloat16 bl = __float2bfloat16(r);
    h = __bfloat16_as_ushort(bh);
    l = __bfloat16_as_ushort(bl);
}

// ============================================================================
// bf16-split tensor-core GEMM, CTA tile 64x128, BK=32, 256 thr (8 warps).
// Warps: 2(m) x 4(n); warp tile 32x32 -> 32 accum regs. 3 CTAs/SM target.
// A may be 2 concatenated passes (npass=2): logical K = npass*K_per_pass.
// B rows are output columns: B[n][k_global], row stride KPb = npass*KPa-ish.
// skipflag: skip the 2nd 16-wide k-step of each pass's LAST chunk (zero pad).
// smem/stage: Ah 4K | Al 4K | Bh 8K | Bl 8K = 24KB. 3 stages = 72KB.
// ============================================================================
#define STAGE_BYTES 24576
#define NSTAGE 3

__global__ __launch_bounds__(256, 3)
void gemm_mma(const bf16* __restrict__ A1h, const bf16* __restrict__ A1l,
              const bf16* __restrict__ A2h, const bf16* __restrict__ A2l,
              int KPa, int nchpp, int npass, int skipflag,
              const bf16* __restrict__ Bh, const bf16* __restrict__ Bl,
              int KPb, int Nvalid,
              float* __restrict__ W1out, float* __restrict__ W2out,
              bf16* __restrict__ out_hi, bf16* __restrict__ out_lo,
              const float* __restrict__ bias,
              int relu_flag, int mode)
{
    extern __shared__ char sm[];
    const uint32_t sb = smem_u32(sm);
    const int tid = threadIdx.x;
    const int lane = tid & 31;
    const int wid = tid >> 5;          // 0..7
    const int widm = wid & 1;          // 0..1 -> m base widm*32
    const int widn = wid >> 1;         // 0..3 -> n base widn*32
    const int rowBase = blockIdx.y * 64;
    const int colBase = blockIdx.x * 128;
    const int T = npass * nchpp;

    auto issue = [&](int c, int s) {
        const uint32_t base = sb + s * STAGE_BYTES;
        int ck = (c >= nchpp) ? c - nchpp : c;
        const bf16* Aph = (c >= nchpp) ? A2h : A1h;
        const bf16* Apl = (c >= nchpp) ? A2l : A1l;
        #pragma unroll
        for (int t = 0; t < 2; t++) {                 // A: 512 x 16B (hi+lo)
            int i = tid + (t << 8);
            int which = i >> 8;
            int rem = i & 255;
            int r = rem >> 2, c16 = rem & 3;
            const bf16* srcb = which ? Apl : Aph;
            uint32_t dst = base + which * 4096 + swz_off(r, c16);
            cpasync16(dst, srcb + (size_t)(rowBase + r) * KPa + ck * 32 + c16 * 8);
        }
        #pragma unroll
        for (int t = 0; t < 4; t++) {                 // B: 1024 x 16B (hi+lo)
            int i = tid + (t << 8);
            int which = i >> 9;
            int rem = i & 511;
            int r = rem >> 2, c16 = rem & 3;
            const bf16* srcb = which ? Bl : Bh;
            uint32_t dst = base + 8192 + which * 8192 + swz_off(r, c16);
            cpasync16(dst, srcb + (size_t)(colBase + r) * KPb + c * 32 + c16 * 8);
        }
        CP_COMMIT();
    };

    float d[2][4][4];
    #pragma unroll
    for (int i = 0; i < 2; i++)
        #pragma unroll
        for (int j = 0; j < 4; j++)
            #pragma unroll
            for (int k = 0; k < 4; k++) d[i][j][k] = 0.f;

    const int lr = lane & 7;
    const int gA_row = ((lane >> 3) & 1) * 8;
    const int gA_c16 = lane >> 4;
    const int gB_row = ((lane >> 4) & 1) * 8;
    const int gB_c16 = (lane >> 3) & 1;

    auto compute_ks = [&](uint32_t base, int ks) {
        uint32_t ah[2][4], al[2][4];
        #pragma unroll
        for (int mt = 0; mt < 2; mt++) {
            int r = widm * 32 + mt * 16 + lr + gA_row;
            int c16 = ks * 2 + gA_c16;
            uint32_t o = swz_off(r, c16);
            ldsm_x4(ah[mt], base + o);
            ldsm_x4(al[mt], base + 4096 + o);
        }
        #pragma unroll
        for (int pr = 0; pr < 2; pr++) {
            int r = widn * 32 + pr * 16 + lr + gB_row;
            int c16 = ks * 2 + gB_c16;
            uint32_t o = swz_off(r, c16);
            {
                uint32_t bh[4];
                ldsm_x4(bh, base + 8192 + o);
                #pragma unroll
                for (int mt = 0; mt < 2; mt++)
                    #pragma unroll
                    for (int oo = 0; oo < 2; oo++) {
                        mma_bf16(d[mt][pr*2+oo], ah[mt], bh[oo*2], bh[oo*2+1]);
                        mma_bf16(d[mt][pr*2+oo], al[mt], bh[oo*2], bh[oo*2+1]);
                    }
            }
            {
                uint32_t bl[4];
                ldsm_x4(bl, base + 16384 + o);
                #pragma unroll
                for (int mt = 0; mt < 2; mt++)
                    #pragma unroll
                    for (int oo = 0; oo < 2; oo++)
                        mma_bf16(d[mt][pr*2+oo], ah[mt], bl[oo*2], bl[oo*2+1]);
            }
        }
    };

    issue(0, 0);
    if (T > 1) issue(1, 1);

    for (int c = 0; c < T; c++) {
        if (c + 1 < T) CP_WAIT(1); else CP_WAIT(0);
        __syncthreads();
        if (c + 2 < T) issue(c + 2, (c + 2) % NSTAGE);

        const uint32_t base = sb + (c % NSTAGE) * STAGE_BYTES;
        compute_ks(base, 0);
        int ck = (c >= nchpp) ? c - nchpp : c;
        if (!(skipflag && ck == nchpp - 1)) compute_ks(base, 1);
    }

    // ---- epilogue ----
    #pragma unroll
    for (int mt = 0; mt < 2; mt++) {
        #pragma unroll
        for (int nt = 0; nt < 4; nt++) {
            int col = colBase + widn * 32 + nt * 8 + (lane & 3) * 2;
            if (col >= Nvalid) continue;
            int row0 = rowBase + widm * 32 + mt * 16 + (lane >> 2);
            float v[4] = { d[mt][nt][0], d[mt][nt][1], d[mt][nt][2], d[mt][nt][3] };
            if (bias) {
                float2 bb = *(const float2*)(bias + col);
                v[0] += bb.x; v[1] += bb.y; v[2] += bb.x; v[3] += bb.y;
            }
            if (relu_flag) {
                #pragma unroll
                for (int k = 0; k < 4; k++) v[k] = fmaxf(v[k], 0.f);
            }
            if (mode & 1) {
                float* basep = (col < 300) ? (W1out + col) : (W2out + (col - 300));
                *(float2*)(basep + (size_t)row0 * KP) = make_float2(v[0], v[1]);
                *(float2*)(basep + (size_t)(row0 + 8) * KP) = make_float2(v[2], v[3]);
            }
            if (mode & 2) {
                uint16_t h0, l0, h1, l1;
                bsplit(v[0], h0, l0); bsplit(v[1], h1, l1);
                *(uint32_t*)(out_hi + (size_t)row0 * KP + col) = (uint32_t)h0 | ((uint32_t)h1 << 16);
                *(uint32_t*)(out_lo + (size_t)row0 * KP + col) = (uint32_t)l0 | ((uint32_t)l1 << 16);
                bsplit(v[2], h0, l0); bsplit(v[3], h1, l1);
                *(uint32_t*)(out_hi + (size_t)(row0 + 8) * KP + col) = (uint32_t)h0 | ((uint32_t)h1 << 16);
                *(uint32_t*)(out_lo + (size_t)(row0 + 8) * KP + col) = (uint32_t)l0 | ((uint32_t)l1 << 16);
            }
        }
    }
}

// ---------------- ONE merged prep kernel (flat dispatch) ---------------------
#define S0 (AF_*300)          // 24600  wfc1
#define S1 (300*300)          // 90000  wG1 (w_neiA)
#define S2 (600*300)          // 180000 wAt (w_atom both halves)
#define S3 (300*600)          // 180000 wF  (w2a | w_fc2)
#define S4 (MROWS*AF_)        // 2099200 split_af
#define BPQ (BROWS*75)        // 2112000 bond float4s
#define PREP_TOTAL (S0+S1+S2+S3+S4+BPQ)

__global__ __launch_bounds__(256)
void prep_all(const float* __restrict__ w_fc1, const float* __restrict__ w_nei,
              const float* __restrict__ w_atom, const float* __restrict__ w2a,
              const float* __restrict__ w_fc2, const float* __restrict__ w2b,
              const float* __restrict__ atom_feats,
              const float* __restrict__ bond_feats,
              bf16* __restrict__ fc1h, bf16* __restrict__ fc1l,
              bf16* __restrict__ G1h, bf16* __restrict__ G1l,
              bf16* __restrict__ Ath, bf16* __restrict__ Atl,
              bf16* __restrict__ Fh, bf16* __restrict__ Fl,
              bf16* __restrict__ afh, bf16* __restrict__ afl,
              float* __restrict__ bW, float* __restrict__ bW2)
{
    int idx = blockIdx.x * blockDim.x + threadIdx.x;
    if (idx < S0) {
        int k = idx / 300, n = idx - k * 300;
        uint16_t h, l; bsplit(w_fc1[idx], h, l);
        fc1h[(size_t)n * KPAF + k] = __ushort_as_bfloat16(h);
        fc1l[(size_t)n * KPAF + k] = __ushort_as_bfloat16(l);
        return;
    }
    idx -= S0;
    if (idx < S1) {
        int k = idx / 300, n = idx - k * 300;
        uint16_t h, l; bsplit(w_nei[idx], h, l);
        G1h[(size_t)n * KP + k] = __ushort_as_bfloat16(h);
        G1l[(size_t)n * KP + k] = __ushort_as_bfloat16(l);
        return;
    }
    idx -= S1;
    if (idx < S2) {
        int k = idx / 300, n = idx - k * 300;
        uint16_t h, l; bsplit(w_atom[idx], h, l);
        int dc = (k < 300) ? k : (320 + k - 300);
        Ath[(size_t)n * 640 + dc] = __ushort_as_bfloat16(h);
        Atl[(size_t)n * 640 + dc] = __ushort_as_bfloat16(l);
        return;
    }
    idx -= S2;
    if (idx < S3) {
        int k = idx / 600, n = idx - k * 600;
        float v = (n < 300) ? w2a[k * 300 + n] : w_fc2[k * 300 + (n - 300)];
        uint16_t h, l; bsplit(v, h, l);
        Fh[(size_t)n * KP + k] = __ushort_as_bfloat16(h);
        Fl[(size_t)n * KP + k] = __ushort_as_bfloat16(l);
        return;
    }
    idx -= S3;
    if (idx < S4) {
        int r = idx / AF_, c = idx - r * AF_;
        uint16_t h, l; bsplit(atom_feats[idx], h, l);
        afh[(size_t)r * KPAF + c] = __ushort_as_bfloat16(h);
        afl[(size_t)r * KPAF + c] = __ushort_as_bfloat16(l);
        return;
    }
    idx -= S4;
    if (idx >= BPQ) return;
    {
        int row = idx / 75;
        int c4 = idx - row * 75;
        const float* f = bond_feats + row * BF_;
        const float4* w1 = (const float4*)(w_nei + (size_t)H_ * H_);   // w_neiB
        const float4* w2 = (const float4*)w2b;
        float4 s1 = make_float4(0.f, 0.f, 0.f, 0.f);
        float4 s2 = make_float4(0.f, 0.f, 0.f, 0.f);
        #pragma unroll
        for (int k = 0; k < BF_; k++) {
            float fk = f[k];
            float4 a = w1[k * 75 + c4];
            float4 b = w2[k * 75 + c4];
            s1.x = fmaf(fk, a.x, s1.x); s1.y = fmaf(fk, a.y, s1.y);
            s1.z = fmaf(fk, a.z, s1.z); s1.w = fmaf(fk, a.w, s1.w);
            s2.x = fmaf(fk, b.x, s2.x); s2.y = fmaf(fk, b.y, s2.y);
            s2.z = fmaf(fk, b.z, s2.z); s2.w = fmaf(fk, b.w, s2.w);
        }
        ((float4*)bW)[idx]  = s1;
        ((float4*)bW2)[idx] = s2;
    }
}

// ---------------- gather+relu+sum -> split nei -------------------------------
__global__ __launch_bounds__(96)
void gather_sum(const float* __restrict__ hW,      // compact, stride KP
                const float* __restrict__ bW,
                const float* __restrict__ b_nei,
                const int* __restrict__ atom_graph,
                const int* __restrict__ bond_graph,
                const int* __restrict__ num_nbs,
                bf16* __restrict__ nei_hi, bf16* __restrict__ nei_lo)
{
    int ba = blockIdx.x;
    __shared__ int hidx[NB_], bidx[NB_];
    __shared__ int nn;
    if (threadIdx.x == 0) nn = num_nbs[ba];
    if (threadIdx.x < NB_) {
        int j = threadIdx.x;
        int ab = atom_graph[((size_t)ba * NB_ + j) * 2 + 0];
        int aa = atom_graph[((size_t)ba * NB_ + j) * 2 + 1];
        hidx[j] = (ab * A_ + aa) * (KP / 4);
        int bb = bond_graph[((size_t)ba * NB_ + j) * 2 + 0];
        int be = bond_graph[((size_t)ba * NB_ + j) * 2 + 1];
        bidx[j] = (bb * BOND_ + be) * (H_ / 4);
    }
    __syncthreads();
    int t = threadIdx.x;
    if (t >= H_ / 4) return;
    int n = nn;
    const float4* h4 = (const float4*)hW;
    const float4* b4 = (const float4*)bW;
    float4 bias4 = ((const float4*)b_nei)[t];
    float4 acc = make_float4(0.f, 0.f, 0.f, 0.f);
    #pragma unroll 2
    for (int j = 0; j < n; j++) {
        float4 hv = h4[hidx[j] + t];
        float4 bv = b4[bidx[j] + t];
        acc.x += fmaxf(hv.x + bv.x + bias4.x, 0.f);
        acc.y += fmaxf(hv.y + bv.y + bias4.y, 0.f);
        acc.z += fmaxf(hv.z + bv.z + bias4.z, 0.f);
        acc.w += fmaxf(hv.w + bv.w + bias4.w, 0.f);
    }
    uint16_t h0, l0, h1, l1, h2, l2, h3, l3;
    bsplit(acc.x, h0, l0); bsplit(acc.y, h1, l1);
    bsplit(acc.z, h2, l2); bsplit(acc.w, h3, l3);
    uint2 ph = make_uint2((uint32_t)h0 | ((uint32_t)h1 << 16), (uint32_t)h2 | ((uint32_t)h3 << 16));
    uint2 pl = make_uint2((uint32_t)l0 | ((uint32_t)l1 << 16), (uint32_t)l2 | ((uint32_t)l3 << 16));
    *(uint2*)(nei_hi + (size_t)ba * KP + t * 4) = ph;
    *(uint2*)(nei_lo + (size_t)ba * KP + t * 4) = pl;
}

// ---------------- final elementwise ------------------------------------------
__global__ __launch_bounds__(96)
void final_k(const float* __restrict__ hw2a,   // compact, stride KP
             const float* __restrict__ hfc2,   // compact, stride KP
             const float* __restrict__ bW2,
             const int* __restrict__ atom_graph,
             const int* __restrict__ bond_graph,
             const int* __restrict__ num_nbs,
             const int* __restrict__ n_atoms,
             float* __restrict__ out)
{
    int ba = blockIdx.x;
    int b = ba / A_;
    int a = ba - b * A_;
    __shared__ int hidx[NB_], bidx[NB_];
    __shared__ int nn, nat;
    if (threadIdx.x == 0) { nn = num_nbs[ba]; nat = n_atoms[b]; }
    if (threadIdx.x < NB_) {
        int j = threadIdx.x;
        int ab = atom_graph[((size_t)ba * NB_ + j) * 2 + 0];
        int aa = atom_graph[((size_t)ba * NB_ + j) * 2 + 1];
        hidx[j] = (ab * A_ + aa) * (KP / 4);
        int bb = bond_graph[((size_t)ba * NB_ + j) * 2 + 0];
        int be = bond_graph[((size_t)ba * NB_ + j) * 2 + 1];
        bidx[j] = (bb * BOND_ + be) * (H_ / 4);
    }
    __syncthreads();
    int t = threadIdx.x;
    if (t >= H_ / 4) return;
    int n = nn;
    bool active = a < nat;
    const float4* A4 = (const float4*)hw2a;
    const float4* B4 = (const float4*)bW2;
    float4 acc = make_float4(0.f, 0.f, 0.f, 0.f);
    #pragma unroll 2
    for (int j = 0; j < n; j++) {
        float4 av = A4[hidx[j] + t];
        float4 bv = B4[bidx[j] + t];
        acc.x = fmaf(av.x, bv.x, acc.x);
        acc.y = fmaf(av.y, bv.y, acc.y);
        acc.z = fmaf(av.z, bv.z, acc.z);
        acc.w = fmaf(av.w, bv.w, acc.w);
    }
    float4 res = make_float4(0.f, 0.f, 0.f, 0.f);
    if (active) {
        float4 fv = ((const float4*)hfc2)[(size_t)ba * (KP / 4) + t];
        res.x = fv.x * acc.x; res.y = fv.y * acc.y;
        res.z = fv.z * acc.z; res.w = fv.w * acc.w;
    }
    ((float4*)out)[(size_t)ba * (H_ / 4) + t] = res;
}

// ---------------- launch ------------------------------------------------------
extern "C" void kernel_launch(void* const* d_in, const int* in_sizes, int n_in,
                              void* d_out, int out_size)
{
    const float* atom_feats = (const float*)d_in[0];
    const float* bond_feats = (const float*)d_in[1];
    const float* w_fc1      = (const float*)d_in[2];
    const float* w_nei      = (const float*)d_in[3];
    const float* b_nei      = (const float*)d_in[4];
    const float* w_atom     = (const float*)d_in[5];
    const float* b_atom     = (const float*)d_in[6];
    const float* w2a        = (const float*)d_in[7];
    const float* w2b        = (const float*)d_in[8];
    const float* w_fc2      = (const float*)d_in[9];
    const int*   atom_graph = (const int*)d_in[10];
    const int*   bond_graph = (const int*)d_in[11];
    const int*   num_nbs    = (const int*)d_in[12];
    const int*   n_atoms    = (const int*)d_in[13];
    float* out = (float*)d_out;

    bf16 *h_hi, *h_lo, *n_hi, *n_lo, *af_hi, *af_lo;
    bf16 *wfc1_hi, *wfc1_lo, *wG1_hi, *wG1_lo, *wAt_hi, *wAt_lo, *wF_hi, *wF_lo;
    float *hW, *hF2, *bW, *bW2;
    cudaGetSymbolAddress((void**)&h_hi, g_h_hi);
    cudaGetSymbolAddress((void**)&h_lo, g_h_lo);
    cudaGetSymbolAddress((void**)&n_hi, g_n_hi);
    cudaGetSymbolAddress((void**)&n_lo, g_n_lo);
    cudaGetSymbolAddress((void**)&af_hi, g_af_hi);
    cudaGetSymbolAddress((void**)&af_lo, g_af_lo);
    cudaGetSymbolAddress((void**)&hW, g_hW);
    cudaGetSymbolAddress((void**)&hF2, g_hF2);
    cudaGetSymbolAddress((void**)&bW, g_bW);
    cudaGetSymbolAddress((void**)&bW2, g_bW2);
    cudaGetSymbolAddress((void**)&wfc1_hi, g_wfc1_hi);
    cudaGetSymbolAddress((void**)&wfc1_lo, g_wfc1_lo);
    cudaGetSymbolAddress((void**)&wG1_hi, g_wG1_hi);
    cudaGetSymbolAddress((void**)&wG1_lo, g_wG1_lo);
    cudaGetSymbolAddress((void**)&wAt_hi, g_wAt_hi);
    cudaGetSymbolAddress((void**)&wAt_lo, g_wAt_lo);
    cudaGetSymbolAddress((void**)&wF_hi, g_wF_hi);
    cudaGetSymbolAddress((void**)&wF_lo, g_wF_lo);

    cudaFuncSetAttribute(gemm_mma, cudaFuncAttributeMaxDynamicSharedMemorySize,
                         NSTAGE * STAGE_BYTES);
    const int SMB = NSTAGE * STAGE_BYTES;
    dim3 gN300(3, MROWS / 64);   // 1200 tiles
    dim3 gN600(5, MROWS / 64);   // 2000 tiles

    // 1: merged prep (weights transpose+split, atom-feat split, bond precompute)
    prep_all<<<(PREP_TOTAL + 255) / 256, 256>>>(
        w_fc1, w_nei, w_atom, w2a, w_fc2, w2b, atom_feats, bond_feats,
        wfc1_hi, wfc1_lo, wG1_hi, wG1_lo, wAt_hi, wAt_lo, wF_hi, wF_lo,
        af_hi, af_lo, bW, bW2);

    // 2: h = relu(af @ w_fc1) -> split   (K=96, all ks needed)
    gemm_mma<<<gN300, 256, SMB>>>(af_hi, af_lo, af_hi, af_lo, KPAF, KPAF / 32, 1, 0,
                                  wfc1_hi, wfc1_lo, KPAF, 300,
                                  nullptr, nullptr, h_hi, h_lo, nullptr, 1, 2);

    for (int it = 0; it < 2; it++) {
        // hW = h @ w_neiA
        gemm_mma<<<gN300, 256, SMB>>>(h_hi, h_lo, h_hi, h_lo, KP, KP / 32, 1, 1,
                                      wG1_hi, wG1_lo, KP, 300,
                                      hW, hW, nullptr, nullptr, nullptr, 0, 1);
        gather_sum<<<MROWS, 96>>>(hW, bW, b_nei, atom_graph, bond_graph,
                                  num_nbs, n_hi, n_lo);
        // h = relu([h | nei] @ w_atom + b_atom)   (npass=2, K=640)
        gemm_mma<<<gN300, 256, SMB>>>(h_hi, h_lo, n_hi, n_lo, KP, KP / 32, 2, 1,
                                      wAt_hi, wAt_lo, 640, 300,
                                      nullptr, nullptr, h_hi, h_lo, b_atom, 1, 2);
    }

    // final: hW = h@w2a ; hF2 = h@w_fc2   (dual compact outputs)
    gemm_mma<<<gN600, 256, SMB>>>(h_hi, h_lo, h_hi, h_lo, KP, KP / 32, 1, 1,
                                  wF_hi, wF_lo, KP, 600,
                                  hW, hF2, nullptr, nullptr, nullptr, 0, 1);
    final_k<<<MROWS, 96>>>(hW, hF2, bW2, atom_graph, bond_graph,
                           num_nbs, n_atoms, out);
}

// round 11
// speedup vs baseline: 1.0853x; 1.0441x over previous
#include <cuda_runtime.h>
#include <cuda_bf16.h>
#include <cstdint>

#define B_ 256
#define A_ 100
#define NB_ 10
#define BOND_ 110
#define AF_ 82
#define BF_ 6
#define H_ 300
#define MROWS (B_*A_)       // 25600
#define BROWS (B_*BOND_)    // 28160
#define KP 320              // padded K stride for H buffers
#define KPAF 96             // padded K stride for atom-feature buffers

typedef __nv_bfloat16 bf16;

// ---------------- scratch (device globals; zero-initialized at load) --------
__device__ __align__(256) bf16  g_h_hi [MROWS*KP];
__device__ __align__(256) bf16  g_h_lo [MROWS*KP];
__device__ __align__(256) bf16  g_n_hi [MROWS*KP];
__device__ __align__(256) bf16  g_n_lo [MROWS*KP];
__device__ __align__(256) bf16  g_af_hi[MROWS*KPAF];
__device__ __align__(256) bf16  g_af_lo[MROWS*KPAF];
__device__ __align__(256) float g_hW   [MROWS*KP];   // compact dense, stride 320
__device__ __align__(256) float g_hF2  [MROWS*KP];   // final hfc2, stride 320
__device__ __align__(256) float g_bW   [BROWS*H_];
__device__ __align__(256) float g_bW2  [BROWS*H_];
// transposed+split weights; 640 rows so any colBase+128 read stays in bounds.
__device__ __align__(256) bf16  g_wfc1_hi[640*KPAF];
__device__ __align__(256) bf16  g_wfc1_lo[640*KPAF];
__device__ __align__(256) bf16  g_wG1_hi[640*KP];    // w_neiA^T  [n][k]
__device__ __align__(256) bf16  g_wG1_lo[640*KP];
__device__ __align__(256) bf16  g_wAt_hi[640*640];   // w_atom^T  [n][k<300->k ; k>=300->320+k-300]
__device__ __align__(256) bf16  g_wAt_lo[640*640];
__device__ __align__(256) bf16  g_wF_hi [640*KP];    // rows 0-299 w2a^T, 300-599 w_fc2^T
__device__ __align__(256) bf16  g_wF_lo [640*KP];

// ---------------- helpers ----------------------------------------------------
__device__ __forceinline__ uint32_t smem_u32(const void* p) {
    uint32_t a;
    asm("{ .reg .u64 t; cvta.to.shared.u64 t, %1; cvt.u32.u64 %0, t; }"
        : "=r"(a) : "l"(p));
    return a;
}
// SW128 layout for a [rows][32 bf16] tile: 2 logical rows per 128B phys row
__device__ __forceinline__ uint32_t swz_off(int r, int c16) {
    uint32_t phys = ((uint32_t)(r >> 1) << 7) | ((uint32_t)(r & 1) << 6) | ((uint32_t)c16 << 4);
    return phys ^ ((phys >> 3) & 0x70);
}
__device__ __forceinline__ void cpasync16(uint32_t dst, const void* src) {
    asm volatile("cp.async.cg.shared.global [%0], [%1], 16;" :: "r"(dst), "l"(src));
}
#define CP_COMMIT() asm volatile("cp.async.commit_group;" ::: "memory")
#define CP_WAIT(n)  asm volatile("cp.async.wait_group %0;" :: "n"(n) : "memory")

__device__ __forceinline__ void ldsm_x4(uint32_t* r, uint32_t addr) {
    asm volatile("ldmatrix.sync.aligned.m8n8.x4.shared.b16 {%0,%1,%2,%3}, [%4];"
        : "=r"(r[0]), "=r"(r[1]), "=r"(r[2]), "=r"(r[3]) : "r"(addr));
}
__device__ __forceinline__ void mma_bf16(float* d, const uint32_t* a,
                                         uint32_t b0, uint32_t b1) {
    asm volatile(
        "mma.sync.aligned.m16n8k16.row.col.f32.bf16.bf16.f32 "
        "{%0,%1,%2,%3}, {%4,%5,%6,%7}, {%8,%9}, {%0,%1,%2,%3};"
        : "+f"(d[0]), "+f"(d[1]), "+f"(d[2]), "+f"(d[3])
        : "r"(a[0]), "r"(a[1]), "r"(a[2]), "r"(a[3]), "r"(b0), "r"(b1));
}
__device__ __forceinline__ void bsplit(float v, uint16_t& h, uint16_t& l) {
    __nv_bfloat16 bh = __float2bfloat16(v);
    float r = v - __bfloat162float(bh);
    __nv_bfloat16 bl = __float2bfloat16(r);
    h = __bfloat16_as_ushort(bh);
    l = __bfloat16_as_ushort(bl);
}

// ============================================================================
// bf16-split tensor-core GEMM, CTA tile 128x128, BK=32, 256 thr (R8 geometry).
// Warps: 4(m) x 2(n); warp tile 32x64. 3 products: AhBh + AlBh + AhBl.
// A may be 2 concatenated passes (npass=2, logical K = npass*KPa).
// B[n][k_global] row stride KPb. skipflag: skip 2nd 16-wide k-step of each
// pass's last chunk (all-zero pad of K=300-in-320 operands).
// Single-barrier 3-stage cp.async pipeline. smem/stage = 32KB, 3 stages.
// ============================================================================
#define STAGE_BYTES 32768
#define NSTAGE 3

__global__ __launch_bounds__(256, 2)
void gemm_mma(const bf16* __restrict__ A1h, const bf16* __restrict__ A1l,
              const bf16* __restrict__ A2h, const bf16* __restrict__ A2l,
              int KPa, int nchpp, int npass, int skipflag,
              const bf16* __restrict__ Bh, const bf16* __restrict__ Bl,
              int KPb, int Nvalid,
              float* __restrict__ W1out, float* __restrict__ W2out,
              bf16* __restrict__ out_hi, bf16* __restrict__ out_lo,
              const float* __restrict__ bias,
              int relu_flag, int mode)
{
    extern __shared__ char sm[];
    const uint32_t sb = smem_u32(sm);
    const int tid = threadIdx.x;
    const int lane = tid & 31;
    const int wid = tid >> 5;
    const int widm = wid & 3;          // 0..3 -> m base widm*32
    const int widn = wid >> 2;         // 0..1 -> n base widn*64
    const int rowBase = blockIdx.y * 128;
    const int colBase = blockIdx.x * 128;
    const int T = npass * nchpp;

    auto issue = [&](int c, int s) {
        const uint32_t base = sb + s * STAGE_BYTES;
        int ck = (c >= nchpp) ? c - nchpp : c;
        const bf16* Aph = (c >= nchpp) ? A2h : A1h;
        const bf16* Apl = (c >= nchpp) ? A2l : A1l;
        #pragma unroll
        for (int t = 0; t < 4; t++) {                 // A: 1024 x 16B (hi+lo)
            int i = tid + (t << 8);
            int which = i >> 9;
            int rem = i & 511;
            int r = rem >> 2, c16 = rem & 3;
            const bf16* srcb = which ? Apl : Aph;
            uint32_t dst = base + which * 8192 + swz_off(r, c16);
            cpasync16(dst, srcb + (size_t)(rowBase + r) * KPa + ck * 32 + c16 * 8);
        }
        #pragma unroll
        for (int t = 0; t < 4; t++) {                 // B: 1024 x 16B (hi+lo)
            int i = tid + (t << 8);
            int which = i >> 9;
            int rem = i & 511;
            int r = rem >> 2, c16 = rem & 3;
            const bf16* srcb = which ? Bl : Bh;
            uint32_t dst = base + 16384 + which * 8192 + swz_off(r, c16);
            cpasync16(dst, srcb + (size_t)(colBase + r) * KPb + c * 32 + c16 * 8);
        }
        CP_COMMIT();
    };

    float d[2][8][4];
    #pragma unroll
    for (int i = 0; i < 2; i++)
        #pragma unroll
        for (int j = 0; j < 8; j++)
            #pragma unroll
            for (int k = 0; k < 4; k++) d[i][j][k] = 0.f;

    const int lr = lane & 7;
    const int gA_row = ((lane >> 3) & 1) * 8;
    const int gA_c16 = lane >> 4;
    const int gB_row = ((lane >> 4) & 1) * 8;
    const int gB_c16 = (lane >> 3) & 1;

    // one 16-wide k-step of the current chunk (R8 register-lean order)
    auto compute_ks = [&](uint32_t base, int ks) {
        uint32_t a[2][2][4];
        #pragma unroll
        for (int mt = 0; mt < 2; mt++) {
            int r = widm * 32 + mt * 16 + lr + gA_row;
            int c16 = ks * 2 + gA_c16;
            uint32_t o = swz_off(r, c16);
            ldsm_x4(a[0][mt], base + o);
            ldsm_x4(a[1][mt], base + 8192 + o);
        }
        #pragma unroll
        for (int pr = 0; pr < 4; pr++) {
            int r = widn * 64 + pr * 16 + lr + gB_row;
            int c16 = ks * 2 + gB_c16;
            uint32_t o = swz_off(r, c16);
            {
                uint32_t bh[4];
                ldsm_x4(bh, base + 16384 + o);
                #pragma unroll
                for (int mt = 0; mt < 2; mt++)
                    #pragma unroll
                    for (int oo = 0; oo < 2; oo++) {
                        mma_bf16(d[mt][pr*2+oo], a[0][mt], bh[oo*2], bh[oo*2+1]);
                        mma_bf16(d[mt][pr*2+oo], a[1][mt], bh[oo*2], bh[oo*2+1]);
                    }
            }
            {
                uint32_t bl[4];
                ldsm_x4(bl, base + 24576 + o);
                #pragma unroll
                for (int mt = 0; mt < 2; mt++)
                    #pragma unroll
                    for (int oo = 0; oo < 2; oo++)
                        mma_bf16(d[mt][pr*2+oo], a[0][mt], bl[oo*2], bl[oo*2+1]);
            }
        }
    };

    issue(0, 0);
    if (T > 1) issue(1, 1);

    for (int c = 0; c < T; c++) {
        if (c + 1 < T) CP_WAIT(1); else CP_WAIT(0);
        __syncthreads();
        if (c + 2 < T) issue(c + 2, (c + 2) % NSTAGE);

        const uint32_t base = sb + (c % NSTAGE) * STAGE_BYTES;
        compute_ks(base, 0);
        int ck = (c >= nchpp) ? c - nchpp : c;
        if (!(skipflag && ck == nchpp - 1)) compute_ks(base, 1);
    }

    // ---- epilogue ----
    #pragma unroll
    for (int mt = 0; mt < 2; mt++) {
        #pragma unroll
        for (int nt = 0; nt < 8; nt++) {
            int col = colBase + widn * 64 + nt * 8 + (lane & 3) * 2;
            if (col >= Nvalid) continue;
            int row0 = rowBase + widm * 32 + mt * 16 + (lane >> 2);
            float v[4] = { d[mt][nt][0], d[mt][nt][1], d[mt][nt][2], d[mt][nt][3] };
            if (bias) {
                float2 bb = *(const float2*)(bias + col);
                v[0] += bb.x; v[1] += bb.y; v[2] += bb.x; v[3] += bb.y;
            }
            if (relu_flag) {
                #pragma unroll
                for (int k = 0; k < 4; k++) v[k] = fmaxf(v[k], 0.f);
            }
            if (mode & 1) {
                float* basep = (col < 300) ? (W1out + col) : (W2out + (col - 300));
                *(float2*)(basep + (size_t)row0 * KP) = make_float2(v[0], v[1]);
                *(float2*)(basep + (size_t)(row0 + 8) * KP) = make_float2(v[2], v[3]);
            }
            if (mode & 2) {
                uint16_t h0, l0, h1, l1;
                bsplit(v[0], h0, l0); bsplit(v[1], h1, l1);
                *(uint32_t*)(out_hi + (size_t)row0 * KP + col) = (uint32_t)h0 | ((uint32_t)h1 << 16);
                *(uint32_t*)(out_lo + (size_t)row0 * KP + col) = (uint32_t)l0 | ((uint32_t)l1 << 16);
                bsplit(v[2], h0, l0); bsplit(v[3], h1, l1);
                *(uint32_t*)(out_hi + (size_t)(row0 + 8) * KP + col) = (uint32_t)h0 | ((uint32_t)h1 << 16);
                *(uint32_t*)(out_lo + (size_t)(row0 + 8) * KP + col) = (uint32_t)l0 | ((uint32_t)l1 << 16);
            }
        }
    }
}

// ---------------- ONE merged prep kernel (flat dispatch) ---------------------
#define S0 (AF_*300)
#define S1 (300*300)
#define S2 (600*300)
#define S3 (300*600)
#define S4 (MROWS*AF_)
#define BPQ (BROWS*75)
#define PREP_TOTAL (S0+S1+S2+S3+S4+BPQ)

__global__ __launch_bounds__(256)
void prep_all(const float* __restrict__ w_fc1, const float* __restrict__ w_nei,
              const float* __restrict__ w_atom, const float* __restrict__ w2a,
              const float* __restrict__ w_fc2, const float* __restrict__ w2b,
              const float* __restrict__ atom_feats,
              const float* __restrict__ bond_feats,
              bf16* __restrict__ fc1h, bf16* __restrict__ fc1l,
              bf16* __restrict__ G1h, bf16* __restrict__ G1l,
              bf16* __restrict__ Ath, bf16* __restrict__ Atl,
              bf16* __restrict__ Fh, bf16* __restrict__ Fl,
              bf16* __restrict__ afh, bf16* __restrict__ afl,
              float* __restrict__ bW, float* __restrict__ bW2)
{
    int idx = blockIdx.x * blockDim.x + threadIdx.x;
    if (idx < S0) {
        int k = idx / 300, n = idx - k * 300;
        uint16_t h, l; bsplit(w_fc1[idx], h, l);
        fc1h[(size_t)n * KPAF + k] = __ushort_as_bfloat16(h);
        fc1l[(size_t)n * KPAF + k] = __ushort_as_bfloat16(l);
        return;
    }
    idx -= S0;
    if (idx < S1) {
        int k = idx / 300, n = idx - k * 300;
        uint16_t h, l; bsplit(w_nei[idx], h, l);
        G1h[(size_t)n * KP + k] = __ushort_as_bfloat16(h);
        G1l[(size_t)n * KP + k] = __ushort_as_bfloat16(l);
        return;
    }
    idx -= S1;
    if (idx < S2) {
        int k = idx / 300, n = idx - k * 300;
        uint16_t h, l; bsplit(w_atom[idx], h, l);
        int dc = (k < 300) ? k : (320 + k - 300);
        Ath[(size_t)n * 640 + dc] = __ushort_as_bfloat16(h);
        Atl[(size_t)n * 640 + dc] = __ushort_as_bfloat16(l);
        return;
    }
    idx -= S2;
    if (idx < S3) {
        int k = idx / 600, n = idx - k * 600;
        float v = (n < 300) ? w2a[k * 300 + n] : w_fc2[k * 300 + (n - 300)];
        uint16_t h, l; bsplit(v, h, l);
        Fh[(size_t)n * KP + k] = __ushort_as_bfloat16(h);
        Fl[(size_t)n * KP + k] = __ushort_as_bfloat16(l);
        return;
    }
    idx -= S3;
    if (idx < S4) {
        int r = idx / AF_, c = idx - r * AF_;
        uint16_t h, l; bsplit(atom_feats[idx], h, l);
        afh[(size_t)r * KPAF + c] = __ushort_as_bfloat16(h);
        afl[(size_t)r * KPAF + c] = __ushort_as_bfloat16(l);
        return;
    }
    idx -= S4;
    if (idx >= BPQ) return;
    {
        int row = idx / 75;
        int c4 = idx - row * 75;
        const float* f = bond_feats + row * BF_;
        const float4* w1 = (const float4*)(w_nei + (size_t)H_ * H_);   // w_neiB
        const float4* w2 = (const float4*)w2b;
        float4 s1 = make_float4(0.f, 0.f, 0.f, 0.f);
        float4 s2 = make_float4(0.f, 0.f, 0.f, 0.f);
        #pragma unroll
        for (int k = 0; k < BF_; k++) {
            float fk = f[k];
            float4 a = w1[k * 75 + c4];
            float4 b = w2[k * 75 + c4];
            s1.x = fmaf(fk, a.x, s1.x); s1.y = fmaf(fk, a.y, s1.y);
            s1.z = fmaf(fk, a.z, s1.z); s1.w = fmaf(fk, a.w, s1.w);
            s2.x = fmaf(fk, b.x, s2.x); s2.y = fmaf(fk, b.y, s2.y);
            s2.z = fmaf(fk, b.z, s2.z); s2.w = fmaf(fk, b.w, s2.w);
        }
        ((float4*)bW)[idx]  = s1;
        ((float4*)bW2)[idx] = s2;
    }
}

// ---------------- gather+relu+sum -> split nei -------------------------------
__global__ __launch_bounds__(96)
void gather_sum(const float* __restrict__ hW,
                const float* __restrict__ bW,
                const float* __restrict__ b_nei,
                const int* __restrict__ atom_graph,
                const int* __restrict__ bond_graph,
                const int* __restrict__ num_nbs,
                bf16* __restrict__ nei_hi, bf16* __restrict__ nei_lo)
{
    int ba = blockIdx.x;
    __shared__ int hidx[NB_], bidx[NB_];
    __shared__ int nn;
    if (threadIdx.x == 0) nn = num_nbs[ba];
    if (threadIdx.x < NB_) {
        int j = threadIdx.x;
        int ab = atom_graph[((size_t)ba * NB_ + j) * 2 + 0];
        int aa = atom_graph[((size_t)ba * NB_ + j) * 2 + 1];
        hidx[j] = (ab * A_ + aa) * (KP / 4);
        int bb = bond_graph[((size_t)ba * NB_ + j) * 2 + 0];
        int be = bond_graph[((size_t)ba * NB_ + j) * 2 + 1];
        bidx[j] = (bb * BOND_ + be) * (H_ / 4);
    }
    __syncthreads();
    int t = threadIdx.x;
    if (t >= H_ / 4) return;
    int n = nn;
    const float4* h4 = (const float4*)hW;
    const float4* b4 = (const float4*)bW;
    float4 bias4 = ((const float4*)b_nei)[t];
    float4 acc = make_float4(0.f, 0.f, 0.f, 0.f);
    #pragma unroll 2
    for (int j = 0; j < n; j++) {
        float4 hv = h4[hidx[j] + t];
        float4 bv = b4[bidx[j] + t];
        acc.x += fmaxf(hv.x + bv.x + bias4.x, 0.f);
        acc.y += fmaxf(hv.y + bv.y + bias4.y, 0.f);
        acc.z += fmaxf(hv.z + bv.z + bias4.z, 0.f);
        acc.w += fmaxf(hv.w + bv.w + bias4.w, 0.f);
    }
    uint16_t h0, l0, h1, l1, h2, l2, h3, l3;
    bsplit(acc.x, h0, l0); bsplit(acc.y, h1, l1);
    bsplit(acc.z, h2, l2); bsplit(acc.w, h3, l3);
    uint2 ph = make_uint2((uint32_t)h0 | ((uint32_t)h1 << 16), (uint32_t)h2 | ((uint32_t)h3 << 16));
    uint2 pl = make_uint2((uint32_t)l0 | ((uint32_t)l1 << 16), (uint32_t)l2 | ((uint32_t)l3 << 16));
    *(uint2*)(nei_hi + (size_t)ba * KP + t * 4) = ph;
    *(uint2*)(nei_lo + (size_t)ba * KP + t * 4) = pl;
}

// ---------------- final elementwise ------------------------------------------
__global__ __launch_bounds__(96)
void final_k(const float* __restrict__ hw2a,
             const float* __restrict__ hfc2,
             const float* __restrict__ bW2,
             const int* __restrict__ atom_graph,
             const int* __restrict__ bond_graph,
             const int* __restrict__ num_nbs,
             const int* __restrict__ n_atoms,
             float* __restrict__ out)
{
    int ba = blockIdx.x;
    int b = ba / A_;
    int a = ba - b * A_;
    __shared__ int hidx[NB_], bidx[NB_];
    __shared__ int nn, nat;
    if (threadIdx.x == 0) { nn = num_nbs[ba]; nat = n_atoms[b]; }
    if (threadIdx.x < NB_) {
        int j = threadIdx.x;
        int ab = atom_graph[((size_t)ba * NB_ + j) * 2 + 0];
        int aa = atom_graph[((size_t)ba * NB_ + j) * 2 + 1];
        hidx[j] = (ab * A_ + aa) * (KP / 4);
        int bb = bond_graph[((size_t)ba * NB_ + j) * 2 + 0];
        int be = bond_graph[((size_t)ba * NB_ + j) * 2 + 1];
        bidx[j] = (bb * BOND_ + be) * (H_ / 4);
    }
    __syncthreads();
    int t = threadIdx.x;
    if (t >= H_ / 4) return;
    int n = nn;
    bool active = a < nat;
    const float4* A4 = (const float4*)hw2a;
    const float4* B4 = (const float4*)bW2;
    float4 acc = make_float4(0.f, 0.f, 0.f, 0.f);
    #pragma unroll 2
    for (int j = 0; j < n; j++) {
        float4 av = A4[hidx[j] + t];
        float4 bv = B4[bidx[j] + t];
        acc.x = fmaf(av.x, bv.x, acc.x);
        acc.y = fmaf(av.y, bv.y, acc.y);
        acc.z = fmaf(av.z, bv.z, acc.z);
        acc.w = fmaf(av.w, bv.w, acc.w);
    }
    float4 res = make_float4(0.f, 0.f, 0.f, 0.f);
    if (active) {
        float4 fv = ((const float4*)hfc2)[(size_t)ba * (KP / 4) + t];
        res.x = fv.x * acc.x; res.y = fv.y * acc.y;
        res.z = fv.z * acc.z; res.w = fv.w * acc.w;
    }
    ((float4*)out)[(size_t)ba * (H_ / 4) + t] = res;
}

// ---------------- launch ------------------------------------------------------
extern "C" void kernel_launch(void* const* d_in, const int* in_sizes, int n_in,
                              void* d_out, int out_size)
{
    const float* atom_feats = (const float*)d_in[0];
    const float* bond_feats = (const float*)d_in[1];
    const float* w_fc1      = (const float*)d_in[2];
    const float* w_nei      = (const float*)d_in[3];
    const float* b_nei      = (const float*)d_in[4];
    const float* w_atom     = (const float*)d_in[5];
    const float* b_atom     = (const float*)d_in[6];
    const float* w2a        = (const float*)d_in[7];
    const float* w2b        = (const float*)d_in[8];
    const float* w_fc2      = (const float*)d_in[9];
    const int*   atom_graph = (const int*)d_in[10];
    const int*   bond_graph = (const int*)d_in[11];
    const int*   num_nbs    = (const int*)d_in[12];
    const int*   n_atoms    = (const int*)d_in[13];
    float* out = (float*)d_out;

    bf16 *h_hi, *h_lo, *n_hi, *n_lo, *af_hi, *af_lo;
    bf16 *wfc1_hi, *wfc1_lo, *wG1_hi, *wG1_lo, *wAt_hi, *wAt_lo, *wF_hi, *wF_lo;
    float *hW, *hF2, *bW, *bW2;
    cudaGetSymbolAddress((void**)&h_hi, g_h_hi);
    cudaGetSymbolAddress((void**)&h_lo, g_h_lo);
    cudaGetSymbolAddress((void**)&n_hi, g_n_hi);
    cudaGetSymbolAddress((void**)&n_lo, g_n_lo);
    cudaGetSymbolAddress((void**)&af_hi, g_af_hi);
    cudaGetSymbolAddress((void**)&af_lo, g_af_lo);
    cudaGetSymbolAddress((void**)&hW, g_hW);
    cudaGetSymbolAddress((void**)&hF2, g_hF2);
    cudaGetSymbolAddress((void**)&bW, g_bW);
    cudaGetSymbolAddress((void**)&bW2, g_bW2);
    cudaGetSymbolAddress((void**)&wfc1_hi, g_wfc1_hi);
    cudaGetSymbolAddress((void**)&wfc1_lo, g_wfc1_lo);
    cudaGetSymbolAddress((void**)&wG1_hi, g_wG1_hi);
    cudaGetSymbolAddress((void**)&wG1_lo, g_wG1_lo);
    cudaGetSymbolAddress((void**)&wAt_hi, g_wAt_hi);
    cudaGetSymbolAddress((void**)&wAt_lo, g_wAt_lo);
    cudaGetSymbolAddress((void**)&wF_hi, g_wF_hi);
    cudaGetSymbolAddress((void**)&wF_lo, g_wF_lo);

    cudaFuncSetAttribute(gemm_mma, cudaFuncAttributeMaxDynamicSharedMemorySize,
                         NSTAGE * STAGE_BYTES);
    const int SMB = NSTAGE * STAGE_BYTES;
    dim3 gN300(3, MROWS / 128);   // 600 CTAs = 2.03 waves @ 2 CTA/SM
    dim3 gN600(5, MROWS / 128);   // 1000 CTAs (final only)

    // 1: merged prep
    prep_all<<<(PREP_TOTAL + 255) / 256, 256>>>(
        w_fc1, w_nei, w_atom, w2a, w_fc2, w2b, atom_feats, bond_feats,
        wfc1_hi, wfc1_lo, wG1_hi, wG1_lo, wAt_hi, wAt_lo, wF_hi, wF_lo,
        af_hi, af_lo, bW, bW2);

    // 2: h = relu(af @ w_fc1)  (K=96 real 82 -> no skip)
    gemm_mma<<<gN300, 256, SMB>>>(af_hi, af_lo, nullptr, nullptr,
                                  KPAF, KPAF / 32, 1, 0,
                                  wfc1_hi, wfc1_lo, KPAF, 300,
                                  nullptr, nullptr, h_hi, h_lo, nullptr, 1, 2);

    for (int it = 0; it < 2; it++) {
        // 3/6: hW = h @ w_neiA   (PROFILED at it=1: launch #6)
        gemm_mma<<<gN300, 256, SMB>>>(h_hi, h_lo, nullptr, nullptr,
                                      KP, KP / 32, 1, 1,
                                      wG1_hi, wG1_lo, KP, 300,
                                      hW, hW, nullptr, nullptr, nullptr, 0, 1);
        // 4/7: gather
        gather_sum<<<MROWS, 96>>>(hW, bW, b_nei, atom_graph, bond_graph,
                                  num_nbs, n_hi, n_lo);
        // 5/8: h = relu([h | nei] @ w_atom + b_atom)  (npass=2, K=640)
        gemm_mma<<<gN300, 256, SMB>>>(h_hi, h_lo, n_hi, n_lo,
                                      KP, KP / 32, 2, 1,
                                      wAt_hi, wAt_lo, 640, 300,
                                      nullptr, nullptr, h_hi, h_lo, b_atom, 1, 2);
    }

    // 9: final  hW = h@w2a ; hF2 = h@w_fc2
    gemm_mma<<<gN600, 256, SMB>>>(h_hi, h_lo, nullptr, nullptr,
                                  KP, KP / 32, 1, 1,
                                  wF_hi, wF_lo, KP, 600,
                                  hW, hF2, nullptr, nullptr, nullptr, 0, 1);
    // 10: final elementwise
    final_k<<<MROWS, 96>>>(hW, hF2, bW2, atom_graph, bond_graph,
                           num_nbs, n_atoms, out);
}